// round 14
// baseline (speedup 1.0000x reference)
#include <cuda_runtime.h>

// InvConditionalLinear forward: per-pixel 32x32 solve W z = x, sum log|det W|.
// B=16, C=32, H=W=48 (HW=2304). 2 matrices per warp x 2 column-parity slices
// (four 8-lane subgroups). Lane owns 4 rows x 8 f32x2 blocks of its parity.
// RANK-2 super-iterations with EXACT trim: in iteration j only slots
// s >= sn = (j+1)>>1 can contain columns >= 2j+2, so head updates sn and the
// stream covers sn+1..7. The j=15 head is dead (no cols >= 32) and skipped.

#define FULL_MASK 0xffffffffu
typedef unsigned long long ull;

static constexpr int B = 16, C = 32, HW = 48 * 48;     // 2304
static constexpr int PIX = 8;                          // pixels per block (128 thr)
static constexpr int RSTR = 36;                        // row stride (floats)
static constexpr int MSTR = 1156;                      // pixel stride: !=0 mod 8 banks
static constexpr int XSTR = 33;                        // s_x/s_z row stride
static constexpr int BLOCKS_PER_BATCH = HW / PIX;      // 288

static __device__ float g_pixlogdet[B * HW];
static __device__ int   g_done[B];

__device__ __forceinline__ ull pack2(float x, float y) {
    ull r;
    asm("mov.b64 %0, {%1, %2};" : "=l"(r) : "r"(__float_as_uint(x)), "r"(__float_as_uint(y)));
    return r;
}
__device__ __forceinline__ float lo32(ull v) { return __uint_as_float((unsigned)v); }
__device__ __forceinline__ float hi32(ull v) { return __uint_as_float((unsigned)(v >> 32)); }
__device__ __forceinline__ ull ffma2(ull a, ull b, ull c) {
    ull d;
    asm("fma.rn.f32x2 %0, %1, %2, %3;" : "=l"(d) : "l"(a), "l"(b), "l"(c));
    return d;
}

__global__ __launch_bounds__(128) void gj_solve_kernel(
    const float* __restrict__ input,     // [B, C, H, W]
    const float* __restrict__ weight,    // [B, C*C, H, W]
    const float* __restrict__ logdet_in, // [B]
    float* __restrict__ out)             // z [B,C,H,W] then logdet [B]
{
    __shared__ float s_w[PIX * MSTR];    // ~37 KB
    __shared__ float s_x[PIX * XSTR];
    __shared__ float s_z[PIX * XSTR];
    __shared__ float s_red[128];
    __shared__ int   s_last;

    const int t    = threadIdx.x;
    const int lane = t & 31;
    const int w    = t >> 5;
    const int q0   = blockIdx.x * PIX;
    const int b    = q0 / HW;
    const int qm0  = q0 - b * HW;

    // ---- Phase 1: coalesced global load, stage to smem (transpose to row-major) ----
    const float* wbase = weight + (size_t)b * (size_t)(C * C) * HW + qm0;
    #pragma unroll
    for (int it = 0; it < 16; ++it) {
        int idx = it * 128 + t;
        int c   = idx >> 1;
        int pp  = (idx & 1) << 2;
        float4 v = *reinterpret_cast<const float4*>(wbase + (size_t)c * HW + pp);
        int sb = (c >> 5) * RSTR + (c & 31);
        s_w[(pp + 0) * MSTR + sb] = v.x;
        s_w[(pp + 1) * MSTR + sb] = v.y;
        s_w[(pp + 2) * MSTR + sb] = v.z;
        s_w[(pp + 3) * MSTR + sb] = v.w;
    }
    #pragma unroll
    for (int it = 0; it < 2; ++it) {
        int c = it * 16 + (t >> 3), pp = t & 7;
        s_x[pp * XSTR + c] = input[(size_t)b * C * HW + (size_t)c * HW + qm0 + pp];
    }
    __syncthreads();

    // ---- Phase 2: rank-2 Gauss-Jordan with exact trim ----
    // mat = lane>>4, par = (lane>>3)&1, sg = lane&7.
    // Lane owns rows sg+8r (r=0..3), f32x2 blocks 2s+par (s=0..7) of matrix mat.
    const int mat = lane >> 4;
    const int par = (lane >> 3) & 1;
    const int sg  = lane & 7;
    const int pix = 2 * w + mat;

    ull d[4][8];
    {
        const float* rb = s_w + pix * MSTR + 2 * par;
        #pragma unroll
        for (int r = 0; r < 4; ++r) {
            const float* rp = rb + (sg + 8 * r) * RSTR;
            #pragma unroll
            for (int s = 0; s < 8; ++s)
                d[r][s] = *reinterpret_cast<const ull*>(rp + 4 * s);
        }
    }
    float rhs[4];
    #pragma unroll
    for (int r = 0; r < 4; ++r)
        rhs[r] = s_x[pix * XSTR + sg + 8 * r];

    float psave[4]  = {1.0f, 1.0f, 1.0f, 1.0f};
    float pisave[4] = {1.0f, 1.0f, 1.0f, 1.0f};

    // loop-carried: nmm[r] = pack2(-M0_r, -M1_r) for the CURRENT block; pivot rhs pair
    ull   nmm[4];
    float r0v, r1v;

    // ---- prologue: multipliers for block 0 (cols 0,1; parity 0; slot 0; rows 0,1) ----
    {
        const ull pb0 = __shfl_sync(FULL_MASK, d[0][0], 0, 16);   // row 0 pivot block
        const ull pb1 = __shfl_sync(FULL_MASK, d[0][0], 1, 16);   // row 1 pivot block
        const float pinv0 = __fdividef(1.0f, lo32(pb0));
        const float c1    = lo32(pb1) * pinv0;
        const float piv1  = fmaf(-c1, hi32(pb0), hi32(pb1));
        const float pinv1 = __fdividef(1.0f, piv1);
        ull mmL[4];
        #pragma unroll
        for (int r = 0; r < 4; ++r) {
            float e0 = lo32(d[r][0]), e1 = hi32(d[r][0]);
            float m0 = e0 * pinv0;
            if (r == 0 && sg == 0 && par == 0) { m0 = 0.0f; psave[0] = e0;   pisave[0] = pinv0; }
            float m1 = fmaf(-m0, hi32(pb0), e1) * pinv1;
            if (r == 0 && sg == 1 && par == 0) { m1 = 0.0f; psave[0] = piv1; pisave[0] = pinv1; }
            const float M0 = fmaf(-m1, c1, m0);
            mmL[r] = pack2(-M0, -m1);
        }
        const int src = (lane & 16) | sg;                          // parity-0 sibling
        #pragma unroll
        for (int r = 0; r < 4; ++r) nmm[r] = __shfl_sync(FULL_MASK, mmL[r], src, 32);
        r0v = __shfl_sync(FULL_MASK, rhs[0], 0, 8);
        r1v = __shfl_sync(FULL_MASK, rhs[0], 1, 8);
    }

    #pragma unroll
    for (int j = 0; j < 16; ++j) {
        const int ow0 = (j & 3) * 2;         // owner lane of row 2j (within subgroup)
        const int ow1 = ow0 + 1;             // owner lane of row 2j+1
        const int tk  = j >> 2;              // owners' local row register index
        const int jn  = j + 1;
        const int sn  = jn >> 1;             // first live slot AND next pivot block slot

        // expand duplicated multiplier pairs for FFMA2
        ull nm0[4], nm1[4];
        #pragma unroll
        for (int r = 0; r < 4; ++r) {
            nm0[r] = pack2(lo32(nmm[r]), lo32(nmm[r]));
            nm1[r] = pack2(hi32(nmm[r]), hi32(nmm[r]));
        }

        // head: broadcast + update the NEXT pivot slot first (j=15: dead, skip)
        if (j < 15) {
            const ull u0 = __shfl_sync(FULL_MASK, d[tk][sn], ow0, 8);
            const ull u1 = __shfl_sync(FULL_MASK, d[tk][sn], ow1, 8);
            #pragma unroll
            for (int r = 0; r < 4; ++r)
                d[r][sn] = ffma2(nm0[r], u0, ffma2(nm1[r], u1, d[r][sn]));
        }

        // prefetch multipliers for block j+1 (overlaps the remaining stream)
        ull mmN[4] = {0, 0, 0, 0};
        if (j < 15) {
            const int pn   = jn & 1;
            const int own0 = (jn & 3) * 2;
            const int own1 = own0 + 1;
            const int tkn  = jn >> 2;
            const ull pb0 = __shfl_sync(FULL_MASK, d[tkn][sn], (pn << 3) | own0, 16);
            const ull pb1 = __shfl_sync(FULL_MASK, d[tkn][sn], (pn << 3) | own1, 16);
            const float pinv0 = __fdividef(1.0f, lo32(pb0));
            const float c1    = lo32(pb1) * pinv0;
            const float piv1  = fmaf(-c1, hi32(pb0), hi32(pb1));
            const float pinv1 = __fdividef(1.0f, piv1);
            ull mmL[4];
            #pragma unroll
            for (int r = 0; r < 4; ++r) {
                float e0 = lo32(d[r][sn]), e1 = hi32(d[r][sn]);
                float m0 = e0 * pinv0;
                if (r == tkn) {
                    if (sg == own0 && par == pn) { m0 = 0.0f; psave[r] = e0;   pisave[r] = pinv0; }
                }
                float m1 = fmaf(-m0, hi32(pb0), e1) * pinv1;
                if (r == tkn) {
                    if (sg == own1 && par == pn) { m1 = 0.0f; psave[r] = piv1; pisave[r] = pinv1; }
                }
                const float M0 = fmaf(-m1, c1, m0);
                mmL[r] = pack2(-M0, -m1);
            }
            const int src = (lane & 16) | (pn << 3) | sg;
            #pragma unroll
            for (int r = 0; r < 4; ++r) mmN[r] = __shfl_sync(FULL_MASK, mmL[r], src, 32);
        }

        // stream remaining live slots (exact trim: sn+1..7)
        #pragma unroll
        for (int s = sn + 1; s < 8; ++s) {
            const ull u0 = __shfl_sync(FULL_MASK, d[tk][s], ow0, 8);
            const ull u1 = __shfl_sync(FULL_MASK, d[tk][s], ow1, 8);
            #pragma unroll
            for (int r = 0; r < 4; ++r)
                d[r][s] = ffma2(nm0[r], u0, ffma2(nm1[r], u1, d[r][s]));
        }

        // rhs rank-2 update with RAW pivot rhs pair
        #pragma unroll
        for (int r = 0; r < 4; ++r)
            rhs[r] = fmaf(lo32(nm0[r]), r0v, fmaf(lo32(nm1[r]), r1v, rhs[r]));

        // rotate pipeline state (pivot rhs read AFTER this iteration's update)
        if (j < 15) {
            const int tkn = jn >> 2;
            r0v = __shfl_sync(FULL_MASK, rhs[tkn], (jn & 3) * 2, 8);
            r1v = __shfl_sync(FULL_MASK, rhs[tkn], (jn & 3) * 2 + 1, 8);
            #pragma unroll
            for (int r = 0; r < 4; ++r) nmm[r] = mmN[r];
        }
    }

    // lane with par == bit1(sg) captured all 4 pivots of its rows; others log(1)=0
    const bool match = (((sg >> 1) & 1) == par);

    float la = __logf(fabsf(psave[0])) + __logf(fabsf(psave[1]))
             + __logf(fabsf(psave[2])) + __logf(fabsf(psave[3]));
    #pragma unroll
    for (int off = 8; off; off >>= 1) la += __shfl_xor_sync(FULL_MASK, la, off, 16);
    if ((lane & 15) == 0) g_pixlogdet[q0 + pix] = la;

    if (match) {
        #pragma unroll
        for (int r = 0; r < 4; ++r)
            s_z[pix * XSTR + sg + 8 * r] = rhs[r] * pisave[r];
    }
    __syncthreads();

    // ---- Phase 3: coalesced store of z ----
    #pragma unroll
    for (int it = 0; it < 2; ++it) {
        int c = it * 16 + (t >> 3), pp = t & 7;
        out[(size_t)b * C * HW + (size_t)c * HW + qm0 + pp] = s_z[pp * XSTR + c];
    }

    // ---- Phase 4: last block per batch reduces the 2304 pixel logdets ----
    __threadfence();
    if (t == 0) {
        int v = atomicAdd(&g_done[b], 1);
        s_last = (v == BLOCKS_PER_BATCH - 1);
    }
    __syncthreads();
    if (s_last) {
        __threadfence();
        float acc = 0.0f;
        #pragma unroll
        for (int r = 0; r < 18; ++r)                 // 2304 = 18 * 128, fixed order
            acc += g_pixlogdet[b * HW + r * 128 + t];
        s_red[t] = acc;
        __syncthreads();
        #pragma unroll
        for (int off = 64; off; off >>= 1) {
            if (t < off) s_red[t] += s_red[t + off];
            __syncthreads();
        }
        if (t == 0) {
            out[(size_t)B * C * HW + b] = logdet_in[b] - s_red[0];
            g_done[b] = 0;                           // reset for next graph replay
        }
    }
}

extern "C" void kernel_launch(void* const* d_in, const int* in_sizes, int n_in,
                              void* d_out, int out_size)
{
    const float* input  = (const float*)d_in[0];
    const float* weight = (const float*)d_in[1];
    const float* logdet = (const float*)d_in[2];
    float* out = (float*)d_out;

    gj_solve_kernel<<<(B * HW) / PIX, 128>>>(input, weight, logdet, out);
}

// round 15
// speedup vs baseline: 1.0069x; 1.0069x over previous
#include <cuda_runtime.h>

// InvConditionalLinear forward: per-pixel 32x32 solve W z = x, sum log|det W|.
// B=16, C=32, H=W=48 (HW=2304). 2 matrices per warp x 2 column-parity slices
// (four 8-lane subgroups). Lane owns 4 rows x 8 f32x2 blocks of its parity.
// RANK-2 super-iterations with exact trim (R14 solver, byte-identical).
// R15: phase-1 channel-pair STS.64 diet (64 STS.32 -> 32 STS.64 per thread)
// and XSTR=36 so phase-3's gather is exactly bank-conflict-free.

#define FULL_MASK 0xffffffffu
typedef unsigned long long ull;

static constexpr int B = 16, C = 32, HW = 48 * 48;     // 2304
static constexpr int PIX = 8;                          // pixels per block (128 thr)
static constexpr int RSTR = 36;                        // row stride (floats)
static constexpr int MSTR = 1156;                      // pixel stride: 4 mod 8 banks
static constexpr int XSTR = 36;                        // s_x/s_z row stride (bank = 4*pp+c)
static constexpr int BLOCKS_PER_BATCH = HW / PIX;      // 288

static __device__ float g_pixlogdet[B * HW];
static __device__ int   g_done[B];

__device__ __forceinline__ ull pack2(float x, float y) {
    ull r;
    asm("mov.b64 %0, {%1, %2};" : "=l"(r) : "r"(__float_as_uint(x)), "r"(__float_as_uint(y)));
    return r;
}
__device__ __forceinline__ float lo32(ull v) { return __uint_as_float((unsigned)v); }
__device__ __forceinline__ float hi32(ull v) { return __uint_as_float((unsigned)(v >> 32)); }
__device__ __forceinline__ ull ffma2(ull a, ull b, ull c) {
    ull d;
    asm("fma.rn.f32x2 %0, %1, %2, %3;" : "=l"(d) : "l"(a), "l"(b), "l"(c));
    return d;
}

__global__ __launch_bounds__(128) void gj_solve_kernel(
    const float* __restrict__ input,     // [B, C, H, W]
    const float* __restrict__ weight,    // [B, C*C, H, W]
    const float* __restrict__ logdet_in, // [B]
    float* __restrict__ out)             // z [B,C,H,W] then logdet [B]
{
    __shared__ float s_w[PIX * MSTR];    // ~37 KB
    __shared__ float s_x[PIX * XSTR];
    __shared__ float s_z[PIX * XSTR];
    __shared__ float s_red[128];
    __shared__ int   s_last;

    const int t    = threadIdx.x;
    const int lane = t & 31;
    const int w    = t >> 5;
    const int q0   = blockIdx.x * PIX;
    const int b    = q0 / HW;
    const int qm0  = q0 - b * HW;

    // ---- Phase 1: coalesced global load, channel-pair packed STS.64 stores ----
    // Thread handles channels (c0, c0+1) for one pixel quad: 2 LDG.128 + 4 STS.64.
    const float* wbase = weight + (size_t)b * (size_t)(C * C) * HW + qm0;
    #pragma unroll
    for (int it = 0; it < 8; ++it) {
        int idx = it * 128 + t;                  // 0..1023
        int h   = idx >> 1;                      // channel-pair id 0..511
        int pp  = (idx & 1) << 2;                // pixel 0 or 4
        int c0  = h << 1;                        // even channel
        float4 v0 = *reinterpret_cast<const float4*>(wbase + (size_t)c0 * HW + pp);
        float4 v1 = *reinterpret_cast<const float4*>(wbase + (size_t)(c0 + 1) * HW + pp);
        float* dst = s_w + (c0 >> 5) * RSTR + (c0 & 31);   // even offset
        *reinterpret_cast<ull*>(dst + (pp + 0) * MSTR) = pack2(v0.x, v1.x);
        *reinterpret_cast<ull*>(dst + (pp + 1) * MSTR) = pack2(v0.y, v1.y);
        *reinterpret_cast<ull*>(dst + (pp + 2) * MSTR) = pack2(v0.z, v1.z);
        *reinterpret_cast<ull*>(dst + (pp + 3) * MSTR) = pack2(v0.w, v1.w);
    }
    #pragma unroll
    for (int it = 0; it < 2; ++it) {
        int c = it * 16 + (t >> 3), pp = t & 7;
        s_x[pp * XSTR + c] = input[(size_t)b * C * HW + (size_t)c * HW + qm0 + pp];
    }
    __syncthreads();

    // ---- Phase 2: rank-2 Gauss-Jordan with exact trim (R14, verbatim) ----
    // mat = lane>>4, par = (lane>>3)&1, sg = lane&7.
    // Lane owns rows sg+8r (r=0..3), f32x2 blocks 2s+par (s=0..7) of matrix mat.
    const int mat = lane >> 4;
    const int par = (lane >> 3) & 1;
    const int sg  = lane & 7;
    const int pix = 2 * w + mat;

    ull d[4][8];
    {
        const float* rb = s_w + pix * MSTR + 2 * par;
        #pragma unroll
        for (int r = 0; r < 4; ++r) {
            const float* rp = rb + (sg + 8 * r) * RSTR;
            #pragma unroll
            for (int s = 0; s < 8; ++s)
                d[r][s] = *reinterpret_cast<const ull*>(rp + 4 * s);
        }
    }
    float rhs[4];
    #pragma unroll
    for (int r = 0; r < 4; ++r)
        rhs[r] = s_x[pix * XSTR + sg + 8 * r];

    float psave[4]  = {1.0f, 1.0f, 1.0f, 1.0f};
    float pisave[4] = {1.0f, 1.0f, 1.0f, 1.0f};

    // loop-carried: nmm[r] = pack2(-M0_r, -M1_r) for the CURRENT block; pivot rhs pair
    ull   nmm[4];
    float r0v, r1v;

    // ---- prologue: multipliers for block 0 (cols 0,1; parity 0; slot 0; rows 0,1) ----
    {
        const ull pb0 = __shfl_sync(FULL_MASK, d[0][0], 0, 16);   // row 0 pivot block
        const ull pb1 = __shfl_sync(FULL_MASK, d[0][0], 1, 16);   // row 1 pivot block
        const float pinv0 = __fdividef(1.0f, lo32(pb0));
        const float c1    = lo32(pb1) * pinv0;
        const float piv1  = fmaf(-c1, hi32(pb0), hi32(pb1));
        const float pinv1 = __fdividef(1.0f, piv1);
        ull mmL[4];
        #pragma unroll
        for (int r = 0; r < 4; ++r) {
            float e0 = lo32(d[r][0]), e1 = hi32(d[r][0]);
            float m0 = e0 * pinv0;
            if (r == 0 && sg == 0 && par == 0) { m0 = 0.0f; psave[0] = e0;   pisave[0] = pinv0; }
            float m1 = fmaf(-m0, hi32(pb0), e1) * pinv1;
            if (r == 0 && sg == 1 && par == 0) { m1 = 0.0f; psave[0] = piv1; pisave[0] = pinv1; }
            const float M0 = fmaf(-m1, c1, m0);
            mmL[r] = pack2(-M0, -m1);
        }
        const int src = (lane & 16) | sg;                          // parity-0 sibling
        #pragma unroll
        for (int r = 0; r < 4; ++r) nmm[r] = __shfl_sync(FULL_MASK, mmL[r], src, 32);
        r0v = __shfl_sync(FULL_MASK, rhs[0], 0, 8);
        r1v = __shfl_sync(FULL_MASK, rhs[0], 1, 8);
    }

    #pragma unroll
    for (int j = 0; j < 16; ++j) {
        const int ow0 = (j & 3) * 2;         // owner lane of row 2j (within subgroup)
        const int ow1 = ow0 + 1;             // owner lane of row 2j+1
        const int tk  = j >> 2;              // owners' local row register index
        const int jn  = j + 1;
        const int sn  = jn >> 1;             // first live slot AND next pivot block slot

        // expand duplicated multiplier pairs for FFMA2
        ull nm0[4], nm1[4];
        #pragma unroll
        for (int r = 0; r < 4; ++r) {
            nm0[r] = pack2(lo32(nmm[r]), lo32(nmm[r]));
            nm1[r] = pack2(hi32(nmm[r]), hi32(nmm[r]));
        }

        // head: broadcast + update the NEXT pivot slot first (j=15: dead, skip)
        if (j < 15) {
            const ull u0 = __shfl_sync(FULL_MASK, d[tk][sn], ow0, 8);
            const ull u1 = __shfl_sync(FULL_MASK, d[tk][sn], ow1, 8);
            #pragma unroll
            for (int r = 0; r < 4; ++r)
                d[r][sn] = ffma2(nm0[r], u0, ffma2(nm1[r], u1, d[r][sn]));
        }

        // prefetch multipliers for block j+1 (overlaps the remaining stream)
        ull mmN[4] = {0, 0, 0, 0};
        if (j < 15) {
            const int pn   = jn & 1;
            const int own0 = (jn & 3) * 2;
            const int own1 = own0 + 1;
            const int tkn  = jn >> 2;
            const ull pb0 = __shfl_sync(FULL_MASK, d[tkn][sn], (pn << 3) | own0, 16);
            const ull pb1 = __shfl_sync(FULL_MASK, d[tkn][sn], (pn << 3) | own1, 16);
            const float pinv0 = __fdividef(1.0f, lo32(pb0));
            const float c1    = lo32(pb1) * pinv0;
            const float piv1  = fmaf(-c1, hi32(pb0), hi32(pb1));
            const float pinv1 = __fdividef(1.0f, piv1);
            ull mmL[4];
            #pragma unroll
            for (int r = 0; r < 4; ++r) {
                float e0 = lo32(d[r][sn]), e1 = hi32(d[r][sn]);
                float m0 = e0 * pinv0;
                if (r == tkn) {
                    if (sg == own0 && par == pn) { m0 = 0.0f; psave[r] = e0;   pisave[r] = pinv0; }
                }
                float m1 = fmaf(-m0, hi32(pb0), e1) * pinv1;
                if (r == tkn) {
                    if (sg == own1 && par == pn) { m1 = 0.0f; psave[r] = piv1; pisave[r] = pinv1; }
                }
                const float M0 = fmaf(-m1, c1, m0);
                mmL[r] = pack2(-M0, -m1);
            }
            const int src = (lane & 16) | (pn << 3) | sg;
            #pragma unroll
            for (int r = 0; r < 4; ++r) mmN[r] = __shfl_sync(FULL_MASK, mmL[r], src, 32);
        }

        // stream remaining live slots (exact trim: sn+1..7)
        #pragma unroll
        for (int s = sn + 1; s < 8; ++s) {
            const ull u0 = __shfl_sync(FULL_MASK, d[tk][s], ow0, 8);
            const ull u1 = __shfl_sync(FULL_MASK, d[tk][s], ow1, 8);
            #pragma unroll
            for (int r = 0; r < 4; ++r)
                d[r][s] = ffma2(nm0[r], u0, ffma2(nm1[r], u1, d[r][s]));
        }

        // rhs rank-2 update with RAW pivot rhs pair
        #pragma unroll
        for (int r = 0; r < 4; ++r)
            rhs[r] = fmaf(lo32(nm0[r]), r0v, fmaf(lo32(nm1[r]), r1v, rhs[r]));

        // rotate pipeline state (pivot rhs read AFTER this iteration's update)
        if (j < 15) {
            const int tkn = jn >> 2;
            r0v = __shfl_sync(FULL_MASK, rhs[tkn], (jn & 3) * 2, 8);
            r1v = __shfl_sync(FULL_MASK, rhs[tkn], (jn & 3) * 2 + 1, 8);
            #pragma unroll
            for (int r = 0; r < 4; ++r) nmm[r] = mmN[r];
        }
    }

    // lane with par == bit1(sg) captured all 4 pivots of its rows; others log(1)=0
    const bool match = (((sg >> 1) & 1) == par);

    float la = __logf(fabsf(psave[0])) + __logf(fabsf(psave[1]))
             + __logf(fabsf(psave[2])) + __logf(fabsf(psave[3]));
    #pragma unroll
    for (int off = 8; off; off >>= 1) la += __shfl_xor_sync(FULL_MASK, la, off, 16);
    if ((lane & 15) == 0) g_pixlogdet[q0 + pix] = la;

    if (match) {
        #pragma unroll
        for (int r = 0; r < 4; ++r)
            s_z[pix * XSTR + sg + 8 * r] = rhs[r] * pisave[r];
    }
    __syncthreads();

    // ---- Phase 3: coalesced store of z (bank = 4*pp + c: conflict-free) ----
    #pragma unroll
    for (int it = 0; it < 2; ++it) {
        int c = it * 16 + (t >> 3), pp = t & 7;
        out[(size_t)b * C * HW + (size_t)c * HW + qm0 + pp] = s_z[pp * XSTR + c];
    }

    // ---- Phase 4: last block per batch reduces the 2304 pixel logdets ----
    __threadfence();
    if (t == 0) {
        int v = atomicAdd(&g_done[b], 1);
        s_last = (v == BLOCKS_PER_BATCH - 1);
    }
    __syncthreads();
    if (s_last) {
        __threadfence();
        float acc = 0.0f;
        #pragma unroll
        for (int r = 0; r < 18; ++r)                 // 2304 = 18 * 128, fixed order
            acc += g_pixlogdet[b * HW + r * 128 + t];
        s_red[t] = acc;
        __syncthreads();
        #pragma unroll
        for (int off = 64; off; off >>= 1) {
            if (t < off) s_red[t] += s_red[t + off];
            __syncthreads();
        }
        if (t == 0) {
            out[(size_t)B * C * HW + b] = logdet_in[b] - s_red[0];
            g_done[b] = 0;                           // reset for next graph replay
        }
    }
}

extern "C" void kernel_launch(void* const* d_in, const int* in_sizes, int n_in,
                              void* d_out, int out_size)
{
    const float* input  = (const float*)d_in[0];
    const float* weight = (const float*)d_in[1];
    const float* logdet = (const float*)d_in[2];
    float* out = (float*)d_out;

    gj_solve_kernel<<<(B * HW) / PIX, 128>>>(input, weight, logdet, out);
}